// round 9
// baseline (speedup 1.0000x reference)
#include <cuda_runtime.h>
#include <cuda_bf16.h>
#include <cstdint>

// ---------------- problem constants ----------------
#define B_ 2
#define T_ 1024
#define S_ 4
#define R_ 32
#define V_ 1023
#define M_ 8
#define ROUTE_VOCAB 65536
#define SUB_STRIDE  (R_ * ROUTE_VOCAB)

#define GM 2048
#define GN 1024
#define GK 256

// ---------------- mma.sync GEMM tiling ----------------
#define BM 128
#define BN 128
#define BK 32
#define NK (GK / BK)               // 8 chunk iterations
#define STAGES 4
#define ROWB 80                    // smem bytes/row: 64B data + 16B pad (conflict-free)
#define STAGE_A (BM * ROWB)
#define STAGE_B (BN * ROWB)
#define STAGE_SZ (STAGE_A + STAGE_B)
#define SMEM_SZ (STAGES * STAGE_SZ)   // 81920

#define TAU 0.005f

// ---------------- device scratch ----------------
__device__ __nv_bfloat16 gA[GM * GK];          // bf16 round of hidden
__device__ __nv_bfloat16 gW[GN * GK];          // bf16 round of q_weight
__device__ float gLog[GM * GN];                // bf16-product logits (fp32 accum)
__device__ __align__(16) unsigned char g_codes[B_ * S_ * T_ * R_];

__device__ __forceinline__ uint32_t smem_u32(const void* p) {
    uint32_t a;
    asm("{ .reg .u64 t; cvta.to.shared.u64 t, %1; cvt.u32.u64 %0, t; }" : "=r"(a) : "l"(p));
    return a;
}

// ---------------- kernel 1: fp32 -> bf16 round ----------------
__global__ __launch_bounds__(256) void split_kernel(const float* __restrict__ A,
                                                    const float* __restrict__ W)
{
    const int NA4 = GM * GK / 4;   // 131072
    const int NW4 = GN * GK / 4;   // 65536
    int i = blockIdx.x * blockDim.x + threadIdx.x;   // 0..196607 exactly
    const float* src; __nv_bfloat16* dst; int b4;
    if (i < NA4) { src = A; dst = gA; b4 = i; }
    else         { src = W; dst = gW; b4 = i - NA4; }

    float4 v = ((const float4*)src)[b4];
    unsigned short l0 = __bfloat16_as_ushort(__float2bfloat16_rn(v.x));
    unsigned short l1 = __bfloat16_as_ushort(__float2bfloat16_rn(v.y));
    unsigned short l2 = __bfloat16_as_ushort(__float2bfloat16_rn(v.z));
    unsigned short l3 = __bfloat16_as_ushort(__float2bfloat16_rn(v.w));
    uint2 u2;
    u2.x = (uint32_t)l0 | ((uint32_t)l1 << 16);
    u2.y = (uint32_t)l2 | ((uint32_t)l3 << 16);
    ((uint2*)dst)[b4] = u2;
}

// ---------------- kernel 2: mma GEMM, epilogue = plain logit store ----------------
__device__ __forceinline__ void load_stage(uint32_t sbase, int c, int bm, int bn, int tid)
{
    int k0 = c * BK;
    const __nv_bfloat16* bA = gA + (size_t)bm * GK + k0;
    const __nv_bfloat16* bW = gW + (size_t)bn * GK + k0;
    uint32_t stg = sbase + (uint32_t)(c % STAGES) * STAGE_SZ;
#pragma unroll
    for (int j = 0; j < 2; ++j) {
        int id  = tid + j * 256;
        int row = id >> 2;
        int c4  = id & 3;
        uint32_t da = stg + (uint32_t)(row * ROWB + c4 * 16);
        asm volatile("cp.async.cg.shared.global [%0], [%1], 16;"
                     :: "r"(da), "l"(bA + (size_t)row * GK + c4 * 8));
        uint32_t db = stg + STAGE_A + (uint32_t)(row * ROWB + c4 * 16);
        asm volatile("cp.async.cg.shared.global [%0], [%1], 16;"
                     :: "r"(db), "l"(bW + (size_t)row * GK + c4 * 8));
    }
    asm volatile("cp.async.commit_group;" ::: "memory");
}

__global__ __launch_bounds__(256, 1)
void gemm_mma_kernel()
{
    extern __shared__ __align__(16) char smem[];
    const uint32_t sbase = smem_u32(smem);
    const int tid  = threadIdx.x;
    const int w    = tid >> 5;
    const int lane = tid & 31;
    const int bm = blockIdx.y * BM, bn = blockIdx.x * BN;
    const int wm = (w & 1) * 64;
    const int wn = (w >> 1) * 32;

    const int lrow = lane & 7;
    const int lmat = lane >> 3;
    const int a_roff = (lmat & 1) * 8 + lrow;
    const int a_koff = (lmat >> 1) * 16;
    const int l16  = lane & 15;
    const int b_roff = l16 & 7;
    const int b_koff = (l16 >> 3) * 16;

    float acc[4][4][4];
#pragma unroll
    for (int i = 0; i < 4; i++)
#pragma unroll
        for (int j = 0; j < 4; j++)
#pragma unroll
            for (int q = 0; q < 4; q++) acc[i][j][q] = 0.0f;

    load_stage(sbase, 0, bm, bn, tid);
    load_stage(sbase, 1, bm, bn, tid);
    load_stage(sbase, 2, bm, bn, tid);

    for (int c = 0; c < NK; ++c) {
        asm volatile("cp.async.wait_group 2;" ::: "memory");
        __syncthreads();
        if (c + 3 < NK) load_stage(sbase, c + 3, bm, bn, tid);

        uint32_t aS = sbase + (uint32_t)(c % STAGES) * STAGE_SZ;
        uint32_t bS = aS + STAGE_A;

#pragma unroll
        for (int kk = 0; kk < 2; ++kk) {
            uint32_t af[4][4];
            uint32_t bf[4][2];
#pragma unroll
            for (int mt = 0; mt < 4; ++mt) {
                uint32_t addr = aS + (uint32_t)((wm + mt * 16 + a_roff) * ROWB + kk * 32 + a_koff);
                asm volatile("ldmatrix.sync.aligned.m8n8.x4.shared.b16 {%0,%1,%2,%3}, [%4];"
                             : "=r"(af[mt][0]), "=r"(af[mt][1]), "=r"(af[mt][2]), "=r"(af[mt][3])
                             : "r"(addr));
            }
#pragma unroll
            for (int nt = 0; nt < 4; ++nt) {
                uint32_t addr = bS + (uint32_t)((wn + nt * 8 + b_roff) * ROWB + kk * 32 + b_koff);
                asm volatile("ldmatrix.sync.aligned.m8n8.x2.shared.b16 {%0,%1}, [%2];"
                             : "=r"(bf[nt][0]), "=r"(bf[nt][1])
                             : "r"(addr));
            }
#pragma unroll
            for (int mt = 0; mt < 4; ++mt)
#pragma unroll
                for (int nt = 0; nt < 4; ++nt) {
                    asm volatile(
                        "mma.sync.aligned.m16n8k16.row.col.f32.bf16.bf16.f32 "
                        "{%0,%1,%2,%3},{%4,%5,%6,%7},{%8,%9},{%0,%1,%2,%3};"
                        : "+f"(acc[mt][nt][0]), "+f"(acc[mt][nt][1]),
                          "+f"(acc[mt][nt][2]), "+f"(acc[mt][nt][3])
                        : "r"(af[mt][0]), "r"(af[mt][1]), "r"(af[mt][2]), "r"(af[mt][3]),
                          "r"(bf[nt][0]), "r"(bf[nt][1]));
                }
        }
    }

    // epilogue: plain coalesced logit store (float2 per fragment pair)
    const int mrow0 = bm + wm + (lane >> 2);
    const int ncol0 = bn + wn + 2 * (lane & 3);
#pragma unroll
    for (int mt = 0; mt < 4; ++mt) {
#pragma unroll
        for (int nt = 0; nt < 4; ++nt) {
            float* p0 = gLog + (size_t)(mrow0 + mt * 16) * GN + ncol0 + nt * 8;
            float* p1 = p0 + 8 * GN;
            *(float2*)p0 = make_float2(acc[mt][nt][0], acc[mt][nt][1]);
            *(float2*)p1 = make_float2(acc[mt][nt][2], acc[mt][nt][3]);
        }
    }
}

// ---------------- kernel 3: sign pack + exact fp32 fixup of near-zeros ----------------
__device__ __noinline__ float dot_fp32(const float* __restrict__ hidden,
                                       const float* __restrict__ qw,
                                       int m, int n)
{
    const float4* pa = (const float4*)(hidden + (size_t)m * GK);
    const float4* pw = (const float4*)(qw + (size_t)n * GK);
    float d = 0.0f;
#pragma unroll 8
    for (int k = 0; k < GK / 4; ++k) {
        float4 a = __ldg(pa + k);
        float4 wv = __ldg(pw + k);
        d = fmaf(a.x, wv.x, d);
        d = fmaf(a.y, wv.y, d);
        d = fmaf(a.z, wv.z, d);
        d = fmaf(a.w, wv.w, d);
    }
    return d;
}

__global__ __launch_bounds__(256)
void pack_kernel(const float* __restrict__ hidden, const float* __restrict__ qw)
{
    int idx = blockIdx.x * blockDim.x + threadIdx.x;   // 0..262143, one code byte each
    int m = idx >> 7;             // 0..2047
    int byteIdx = idx & 127;      // 0..127
    int n0 = byteIdx * 8;

    const float4* p = (const float4*)(gLog + (size_t)m * GN + n0);
    float4 v0 = p[0];
    float4 v1 = p[1];
    float v[8] = {v0.x, v0.y, v0.z, v0.w, v1.x, v1.y, v1.z, v1.w};

    unsigned byte = 0;
#pragma unroll
    for (int j = 0; j < 8; ++j)
        if (v[j] > 0.0f) byte |= (1u << j);

    // exact fixup for near-zero logits (rare: ~1.25% of logits)
#pragma unroll
    for (int j = 0; j < 8; ++j) {
        if (fabsf(v[j]) < TAU) {
            float d = dot_fp32(hidden, qw, m, n0 + j);
            byte = (byte & ~(1u << j)) | ((d > 0.0f) ? (1u << j) : 0u);
        }
    }

    int b = m >> 10;
    int t = m & 1023;
    int s = byteIdx >> 5;
    int r = byteIdx & 31;
    g_codes[((size_t)((b * S_ + s) * T_ + t) * R_) + r] = (unsigned char)byte;
}

// ---------------- kernel 4: gather (ILP 4, straight-line) ----------------
#define NUNITS (B_ * S_ * V_ * R_ * 2)      // 523776
#define GSTRIDE 131072                       // 512 blocks * 256 threads
__global__ __launch_bounds__(256)
void gather_kernel(const float* __restrict__ flat, float* __restrict__ out)
{
    const int tid0 = blockIdx.x * blockDim.x + threadIdx.x;

    const float4* s0; const float4* s1; const float4* s2; const float4* s3;
    float4 *d0, *d1, *d2, *d3;
    bool p3;

    {
        int idx = tid0;
        int half = idx & 1;  int row = idx >> 1;
        int r = row & 31;    int q = row >> 5;
        int v = q % V_;      int bs = q / V_;
        unsigned addr = (unsigned)g_codes[(size_t)(bs * T_ + v) * R_ + r]
                      | ((unsigned)g_codes[(size_t)(bs * T_ + v) * R_ + r + R_] << 8);
        unsigned gidx = (unsigned)(bs & 3) * SUB_STRIDE + (unsigned)r * ROUTE_VOCAB + addr;
        s0 = (const float4*)(flat + (size_t)gidx * M_) + half;
        d0 = (float4*)(out + (size_t)row * M_) + half;
    }
    {
        int idx = tid0 + GSTRIDE;
        int half = idx & 1;  int row = idx >> 1;
        int r = row & 31;    int q = row >> 5;
        int v = q % V_;      int bs = q / V_;
        unsigned addr = (unsigned)g_codes[(size_t)(bs * T_ + v) * R_ + r]
                      | ((unsigned)g_codes[(size_t)(bs * T_ + v) * R_ + r + R_] << 8);
        unsigned gidx = (unsigned)(bs & 3) * SUB_STRIDE + (unsigned)r * ROUTE_VOCAB + addr;
        s1 = (const float4*)(flat + (size_t)gidx * M_) + half;
        d1 = (float4*)(out + (size_t)row * M_) + half;
    }
    {
        int idx = tid0 + 2 * GSTRIDE;
        int half = idx & 1;  int row = idx >> 1;
        int r = row & 31;    int q = row >> 5;
        int v = q % V_;      int bs = q / V_;
        unsigned addr = (unsigned)g_codes[(size_t)(bs * T_ + v) * R_ + r]
                      | ((unsigned)g_codes[(size_t)(bs * T_ + v) * R_ + r + R_] << 8);
        unsigned gidx = (unsigned)(bs & 3) * SUB_STRIDE + (unsigned)r * ROUTE_VOCAB + addr;
        s2 = (const float4*)(flat + (size_t)gidx * M_) + half;
        d2 = (float4*)(out + (size_t)row * M_) + half;
    }
    {
        int idx = tid0 + 3 * GSTRIDE;
        p3 = idx < NUNITS;
        int cidx = p3 ? idx : 0;
        int half = cidx & 1;  int row = cidx >> 1;
        int r = row & 31;     int q = row >> 5;
        int v = q % V_;       int bs = q / V_;
        unsigned addr = (unsigned)g_codes[(size_t)(bs * T_ + v) * R_ + r]
                      | ((unsigned)g_codes[(size_t)(bs * T_ + v) * R_ + r + R_] << 8);
        unsigned gidx = (unsigned)(bs & 3) * SUB_STRIDE + (unsigned)r * ROUTE_VOCAB + addr;
        s3 = (const float4*)(flat + (size_t)gidx * M_) + half;
        d3 = (float4*)(out + (size_t)row * M_) + half;
    }

    float4 v0 = __ldg(s0);
    float4 v1 = __ldg(s1);
    float4 v2 = __ldg(s2);
    float4 v3 = p3 ? __ldg(s3) : make_float4(0.f, 0.f, 0.f, 0.f);

    *d0 = v0;
    *d1 = v1;
    *d2 = v2;
    if (p3) *d3 = v3;
}

// ---------------- launch ----------------
extern "C" void kernel_launch(void* const* d_in, const int* in_sizes, int n_in,
                              void* d_out, int out_size)
{
    (void)in_sizes; (void)n_in; (void)out_size;
    const float* hidden = (const float*)d_in[0];
    const float* qw     = (const float*)d_in[1];
    const float* fw     = (const float*)d_in[2];
    float* out          = (float*)d_out;

    cudaFuncSetAttribute(gemm_mma_kernel, cudaFuncAttributeMaxDynamicSharedMemorySize, SMEM_SZ);

    split_kernel<<<768, 256>>>(hidden, qw);

    dim3 grid(GN / BN, GM / BM);   // (8, 16)
    gemm_mma_kernel<<<grid, 256, SMEM_SZ>>>();

    pack_kernel<<<1024, 256>>>(hidden, qw);

    gather_kernel<<<512, 256>>>(fw, out);
}